// round 3
// baseline (speedup 1.0000x reference)
#include <cuda_runtime.h>

#define MM   64      // nodes per graph
#define HH   128     // hidden
#define INF_ 3       // input feats
#define AA   64      // A
#define STR  132     // padded row stride (floats)
#define NT   512     // threads per CTA

__device__ float g_c2l[HH], g_c2r[HH], g_c1l[INF_], g_c1r[INF_];

// Precompute c = W @ a_half vectors (tiny, once per launch, graph-capturable)
__global__ void precomp_kernel(const float* __restrict__ W1, const float* __restrict__ a1,
                               const float* __restrict__ W2, const float* __restrict__ a2) {
    int t = threadIdx.x;  // 128 threads
    float s1 = 0.f, s2 = 0.f;
#pragma unroll 8
    for (int j = 0; j < HH; j++) {
        float w = W2[t * HH + j];
        s1 = fmaf(w, a2[j], s1);
        s2 = fmaf(w, a2[HH + j], s2);
    }
    g_c2l[t] = s1;
    g_c2r[t] = s2;
    if (t < INF_) {
        float p = 0.f, q = 0.f;
#pragma unroll 8
        for (int j = 0; j < HH; j++) {
            float w = W1[t * HH + j];
            p = fmaf(w, a1[j], p);
            q = fmaf(w, a1[HH + j], q);
        }
        g_c1l[t] = p;
        g_c1r[t] = q;
    }
}

// Softmax over 64 cols, 8 lanes per row (512 threads -> 64 rows x 8 lanes).
__device__ __forceinline__ void softmax64_w8(float* __restrict__ sAt,
                                             const float* __restrict__ sSi,
                                             const float* __restrict__ sSj, int tid) {
    int row = tid >> 3, lane = tid & 7;
    float si = sSi[row];
    const float* sj = sSj + lane * 8;
    float ev[8];
    float m = -1e30f;
#pragma unroll
    for (int j = 0; j < 8; j++) {
        float x = si + sj[j];
        x = (x > 0.f) ? x : 0.2f * x;  // leaky_relu alpha=0.2
        ev[j] = x;
        m = fmaxf(m, x);
    }
    m = fmaxf(m, __shfl_xor_sync(0xffffffffu, m, 1));
    m = fmaxf(m, __shfl_xor_sync(0xffffffffu, m, 2));
    m = fmaxf(m, __shfl_xor_sync(0xffffffffu, m, 4));
    float s = 0.f;
#pragma unroll
    for (int j = 0; j < 8; j++) {
        float e = __expf(ev[j] - m);
        ev[j] = e;
        s += e;
    }
    s += __shfl_xor_sync(0xffffffffu, s, 1);
    s += __shfl_xor_sync(0xffffffffu, s, 2);
    s += __shfl_xor_sync(0xffffffffu, s, 4);
    float inv = 1.0f / s;
    float* dst = sAt + row * AA + lane * 8;
#pragma unroll
    for (int j = 0; j < 8; j++) dst[j] = ev[j] * inv;
}

__global__ __launch_bounds__(NT, 2) void gat_kernel(
    const float* __restrict__ users, const float* __restrict__ W1,
    const float* __restrict__ W2,
    const float* __restrict__ mw1, const float* __restrict__ mb1,
    const float* __restrict__ mw2, const float* __restrict__ mb2,
    float* __restrict__ out, int B) {
    extern __shared__ float sm[];
    float* sWh   = sm;                    // 64*132  (Wh2)
    float* sH    = sWh + MM * STR;        // 64*132  (h after layer 1)
    float* sAt   = sH + MM * STR;         // 64*64
    float* sU    = sAt + MM * AA;         // 192
    float* sT    = sU + 192;              // 256 (64 x 4, T = attn1 @ U padded)
    float* sSi   = sT + 256;              // 64
    float* sSj   = sSi + 64;              // 64
    float* sC2l  = sSj + 64;              // 128
    float* sC2r  = sC2l + 128;            // 128
    float* sPool4= sC2r + 128;            // 512 (4 quarters x 128)
    float* sPool = sPool4 + 512;          // 128
    float* sR    = sPool + 128;           // 32
    float* sO    = sR + 32;               // 128
    float* sSum  = sO + 128;              // 2

    const int tid = threadIdx.x;
    const int d = tid & 127;     // output column
    const int q = tid >> 7;      // row quarter: rows q*16 .. q*16+15
    const int b = blockIdx.x;

    // ---- P0: load users + c2 vectors
    if (tid < MM * INF_) sU[tid] = users[b * (MM * INF_) + tid];
    if (tid < 128) { sC2l[tid] = g_c2l[tid]; sC2r[tid] = g_c2r[tid]; }
    __syncthreads();

    // ---- P1: layer1 si/sj via c1 trick (3 FMAs per row)
    if (tid < MM) {
        float u0 = sU[tid * 3], u1 = sU[tid * 3 + 1], u2 = sU[tid * 3 + 2];
        sSi[tid] = u0 * g_c1l[0] + u1 * g_c1l[1] + u2 * g_c1l[2];
        sSj[tid] = u0 * g_c1r[0] + u1 * g_c1r[1] + u2 * g_c1r[2];
    }
    __syncthreads();

    // ---- P2: softmax layer 1 (all 512 threads)
    softmax64_w8(sAt, sSi, sSj, tid);
    __syncthreads();

    // ---- P3a: T = attn1 @ U  (64 x 3, rank-3 fusion: attn1@(U@W1) = (attn1@U)@W1)
    {
        int row = tid >> 3, lane = tid & 7;
        const float* arow = sAt + row * AA + lane * 8;
        float t0 = 0.f, t1 = 0.f, t2 = 0.f;
#pragma unroll
        for (int j = 0; j < 8; j++) {
            float a = arow[j];
            const float* u = sU + (lane * 8 + j) * 3;
            t0 = fmaf(a, u[0], t0);
            t1 = fmaf(a, u[1], t1);
            t2 = fmaf(a, u[2], t2);
        }
#pragma unroll
        for (int off = 1; off < 8; off <<= 1) {
            t0 += __shfl_xor_sync(0xffffffffu, t0, off);
            t1 += __shfl_xor_sync(0xffffffffu, t1, off);
            t2 += __shfl_xor_sync(0xffffffffu, t2, off);
        }
        if (!lane) {
            sT[row * 4 + 0] = t0;
            sT[row * 4 + 1] = t1;
            sT[row * 4 + 2] = t2;
            sT[row * 4 + 3] = 0.f;
        }
    }
    __syncthreads();

    // ---- P3b: h = elu(T @ W1) -> sH  (K=3, trivially cheap)
    {
        float w0 = W1[d], w1 = W1[HH + d], w2 = W1[2 * HH + d];
        const int i0 = q * 16;
#pragma unroll
        for (int r = 0; r < 16; r++) {
            float4 t = *(const float4*)&sT[(i0 + r) * 4];
            float x = fmaf(t.x, w0, fmaf(t.y, w1, t.z * w2));
            sH[(i0 + r) * STR + d] = (x > 0.f) ? x : (__expf(x) - 1.0f);
        }
    }
    __syncthreads();

    // ---- P4: layer2 si/sj = h @ c2 (64 rows x 8 lanes, 16 k each)
    {
        int row = tid >> 3, lane = tid & 7;
        const float* hr = sH + row * STR + lane * 16;
        const float* cl = sC2l + lane * 16;
        const float* cr = sC2r + lane * 16;
        float s1 = 0.f, s2 = 0.f;
#pragma unroll
        for (int k = 0; k < 16; k++) {
            float hv = hr[k];
            s1 = fmaf(hv, cl[k], s1);
            s2 = fmaf(hv, cr[k], s2);
        }
        s1 += __shfl_xor_sync(0xffffffffu, s1, 1);
        s2 += __shfl_xor_sync(0xffffffffu, s2, 1);
        s1 += __shfl_xor_sync(0xffffffffu, s1, 2);
        s2 += __shfl_xor_sync(0xffffffffu, s2, 2);
        s1 += __shfl_xor_sync(0xffffffffu, s1, 4);
        s2 += __shfl_xor_sync(0xffffffffu, s2, 4);
        if (!lane) { sSi[row] = s1; sSj[row] = s2; }
    }
    // ---- P5: Wh2 = h @ W2 -> sWh (16 rows per thread)
    {
        const int i0 = q * 16;
        float acc[16];
#pragma unroll
        for (int r = 0; r < 16; r++) acc[r] = 0.f;
        for (int k0 = 0; k0 < HH; k0 += 4) {
            float w0 = W2[(k0 + 0) * HH + d];
            float w1 = W2[(k0 + 1) * HH + d];
            float w2 = W2[(k0 + 2) * HH + d];
            float w3 = W2[(k0 + 3) * HH + d];
#pragma unroll
            for (int r = 0; r < 16; r++) {
                float4 h4 = *(const float4*)&sH[(i0 + r) * STR + k0];
                acc[r] = fmaf(h4.x, w0, acc[r]);
                acc[r] = fmaf(h4.y, w1, acc[r]);
                acc[r] = fmaf(h4.z, w2, acc[r]);
                acc[r] = fmaf(h4.w, w3, acc[r]);
            }
        }
#pragma unroll
        for (int r = 0; r < 16; r++) sWh[(i0 + r) * STR + d] = acc[r];
    }
    __syncthreads();

    // ---- P6: softmax layer 2
    softmax64_w8(sAt, sSi, sSj, tid);
    __syncthreads();

    // ---- P7: h2 = elu(attn2 @ Wh2) fused with partial max-pool
    {
        const int i0 = q * 16;
        float acc[16];
#pragma unroll
        for (int r = 0; r < 16; r++) acc[r] = 0.f;
        for (int k0 = 0; k0 < MM; k0 += 4) {
            float w0 = sWh[(k0 + 0) * STR + d];
            float w1 = sWh[(k0 + 1) * STR + d];
            float w2 = sWh[(k0 + 2) * STR + d];
            float w3 = sWh[(k0 + 3) * STR + d];
#pragma unroll
            for (int r = 0; r < 16; r++) {
                float4 a4 = *(const float4*)&sAt[(i0 + r) * AA + k0];
                acc[r] = fmaf(a4.x, w0, acc[r]);
                acc[r] = fmaf(a4.y, w1, acc[r]);
                acc[r] = fmaf(a4.z, w2, acc[r]);
                acc[r] = fmaf(a4.w, w3, acc[r]);
            }
        }
        float pool = -1e30f;
#pragma unroll
        for (int r = 0; r < 16; r++) {
            float x = acc[r];
            float v = (x > 0.f) ? x : (__expf(x) - 1.0f);
            pool = fmaxf(pool, v);
        }
        sPool4[q * 128 + d] = pool;
    }
    __syncthreads();

    // ---- P7b: reduce pool over the 4 quarters
    if (tid < 128) {
        float p0 = sPool4[tid],        p1 = sPool4[128 + tid];
        float p2 = sPool4[256 + tid],  p3 = sPool4[384 + tid];
        sPool[tid] = fmaxf(fmaxf(p0, p1), fmaxf(p2, p3));
    }
    __syncthreads();

    // ---- P8: hidden = relu(pooled @ mw1 + mb1)  (32 cols x 8 lanes)
    if (tid < 256) {
        int col = tid >> 3, lane = tid & 7;
        float acc = 0.f;
        const float* pp = sPool + lane * 16;
#pragma unroll
        for (int k = 0; k < 16; k++) acc = fmaf(pp[k], mw1[(lane * 16 + k) * 32 + col], acc);
        acc += __shfl_xor_sync(0xffffffffu, acc, 1);
        acc += __shfl_xor_sync(0xffffffffu, acc, 2);
        acc += __shfl_xor_sync(0xffffffffu, acc, 4);
        if (!lane) sR[col] = fmaxf(acc + mb1[col], 0.f);
    }
    __syncthreads();

    // ---- P9: readout = hidden @ mw2 + mb2; relu + eps
    if (tid < 128) {
        float acc = mb2[tid];
#pragma unroll
        for (int m = 0; m < 32; m++) acc = fmaf(sR[m], mw2[m * HH + tid], acc);
        sO[tid] = fmaxf(acc, 0.f) + 1e-6f;
    }
    __syncthreads();

    // ---- P10: sums (delta = first 64, power = last 64)
    if (tid < 2) {
        float s = 0.f;
        const float* p = sO + tid * 64;
#pragma unroll 8
        for (int j = 0; j < 64; j++) s += p[j];
        sSum[tid] = s;
    }
    __syncthreads();

    // ---- P11: normalize & write. Output layout: power[B,A] then delta[B,A]
    if (tid < 128) {
        const float Bmax = 2.0f * 50.0f - 63.0f * 0.025f;  // 98.425
        const float PMAX = 1.0f;                            // 10^(30/10-3)
        if (tid < 64) {
            out[(size_t)B * AA + (size_t)b * AA + tid] = Bmax * sO[tid] / (sSum[0] + 1e-6f);
        } else {
            out[(size_t)b * AA + (tid - 64)] = PMAX * sO[tid] / (sSum[1] + 1e-6f);
        }
    }
}

static const int SMEM_FLOATS = 2 * MM * STR + MM * AA + 192 + 256 + 64 + 64 + 128 + 128 + 512 + 128 + 32 + 128 + 2;

extern "C" void kernel_launch(void* const* d_in, const int* in_sizes, int n_in,
                              void* d_out, int out_size) {
    const float* users = (const float*)d_in[0];
    const float* W1    = (const float*)d_in[1];
    const float* a1    = (const float*)d_in[2];
    const float* W2    = (const float*)d_in[3];
    const float* a2    = (const float*)d_in[4];
    const float* mw1   = (const float*)d_in[5];
    const float* mb1   = (const float*)d_in[6];
    const float* mw2   = (const float*)d_in[7];
    const float* mb2   = (const float*)d_in[8];
    float* out = (float*)d_out;

    int B = in_sizes[0] / (MM * INF_);
    size_t smem = (size_t)SMEM_FLOATS * sizeof(float);

    cudaFuncSetAttribute(gat_kernel, cudaFuncAttributeMaxDynamicSharedMemorySize, (int)smem);

    precomp_kernel<<<1, 128>>>(W1, a1, W2, a2);
    gat_kernel<<<B, NT, smem>>>(users, W1, W2, mw1, mb1, mw2, mb2, out, B);
}

// round 4
// speedup vs baseline: 1.1300x; 1.1300x over previous
#include <cuda_runtime.h>

#define MM   64      // nodes per graph
#define HH   128     // hidden
#define INF_ 3       // input feats
#define AA   64      // A
#define STR  132     // padded row stride (floats)
#define NT   512     // threads per CTA

__device__ float g_c2l[HH], g_c2r[HH], g_c1l[INF_], g_c1r[INF_];

__global__ void precomp_kernel(const float* __restrict__ W1, const float* __restrict__ a1,
                               const float* __restrict__ W2, const float* __restrict__ a2) {
    int t = threadIdx.x;  // 128 threads
    float s1 = 0.f, s2 = 0.f;
#pragma unroll 8
    for (int j = 0; j < HH; j++) {
        float w = W2[t * HH + j];
        s1 = fmaf(w, a2[j], s1);
        s2 = fmaf(w, a2[HH + j], s2);
    }
    g_c2l[t] = s1;
    g_c2r[t] = s2;
    if (t < INF_) {
        float p = 0.f, q = 0.f;
#pragma unroll 8
        for (int j = 0; j < HH; j++) {
            float w = W1[t * HH + j];
            p = fmaf(w, a1[j], p);
            q = fmaf(w, a1[HH + j], q);
        }
        g_c1l[t] = p;
        g_c1r[t] = q;
    }
}

// Softmax over 64 cols, 8 lanes per row (512 threads -> 64 rows x 8 lanes).
__device__ __forceinline__ void softmax64_w8(float* __restrict__ sAt,
                                             const float* __restrict__ sSi,
                                             const float* __restrict__ sSj, int tid) {
    int row = tid >> 3, lane = tid & 7;
    float si = sSi[row];
    const float* sj = sSj + lane * 8;
    float ev[8];
    float m = -1e30f;
#pragma unroll
    for (int j = 0; j < 8; j++) {
        float x = si + sj[j];
        x = (x > 0.f) ? x : 0.2f * x;  // leaky_relu alpha=0.2
        ev[j] = x;
        m = fmaxf(m, x);
    }
    m = fmaxf(m, __shfl_xor_sync(0xffffffffu, m, 1));
    m = fmaxf(m, __shfl_xor_sync(0xffffffffu, m, 2));
    m = fmaxf(m, __shfl_xor_sync(0xffffffffu, m, 4));
    float s = 0.f;
#pragma unroll
    for (int j = 0; j < 8; j++) {
        float e = __expf(ev[j] - m);
        ev[j] = e;
        s += e;
    }
    s += __shfl_xor_sync(0xffffffffu, s, 1);
    s += __shfl_xor_sync(0xffffffffu, s, 2);
    s += __shfl_xor_sync(0xffffffffu, s, 4);
    float inv = 1.0f / s;
    float* dst = sAt + row * AA + lane * 8;
#pragma unroll
    for (int j = 0; j < 8; j++) dst[j] = ev[j] * inv;
}

__device__ __forceinline__ float elu1(float x) {
    return (x > 0.f) ? x : (__expf(x) - 1.0f);
}

__global__ __launch_bounds__(NT, 2) void gat_kernel(
    const float* __restrict__ users, const float* __restrict__ W1,
    const float* __restrict__ W2,
    const float* __restrict__ mw1, const float* __restrict__ mb1,
    const float* __restrict__ mw2, const float* __restrict__ mb2,
    float* __restrict__ out, int B) {
    extern __shared__ float sm[];
    float* sWh   = sm;                    // 64*132
    float* sH    = sWh + MM * STR;        // 64*132
    float* sAt   = sH + MM * STR;         // 64*64
    float* sU    = sAt + MM * AA;         // 192
    float* sSi   = sU + 192;              // 64
    float* sSj   = sSi + 64;              // 64
    float* sC2l  = sSj + 64;              // 128
    float* sC2r  = sC2l + 128;            // 128
    float* sPool = sC2r + 128;            // 128
    float* sR    = sPool + 128;           // 32
    float* sO    = sR + 32;               // 128
    float* sSum  = sO + 128;              // 2

    const int tid  = threadIdx.x;
    const int b    = blockIdx.x;
    // GEMM decomposition: warp tile = 64 rows x 8 cols; thread = 8 rows x 2 cols
    const int warp = tid >> 5;           // 16 warps -> col octet
    const int lane = tid & 31;
    const int rg8  = lane >> 2;          // 0..7 row sub-group (rows rg8, rg8+8, ...)
    const int cp   = lane & 3;           // 0..3 col pair
    const int c0   = warp * 8 + cp * 2;  // first of 2 columns

    // ---- P0: load users + c2 vectors
    if (tid < MM * INF_) sU[tid] = users[b * (MM * INF_) + tid];
    if (tid < 128) { sC2l[tid] = g_c2l[tid]; sC2r[tid] = g_c2r[tid]; }
    __syncthreads();

    // ---- P1: layer1 si/sj via c1 trick
    if (tid < MM) {
        float u0 = sU[tid * 3], u1 = sU[tid * 3 + 1], u2 = sU[tid * 3 + 2];
        sSi[tid] = u0 * g_c1l[0] + u1 * g_c1l[1] + u2 * g_c1l[2];
        sSj[tid] = u0 * g_c1r[0] + u1 * g_c1r[1] + u2 * g_c1r[2];
    }
    // ---- P1b: Wh1 = users @ W1 (thread = (quarter, column))
    {
        const int d = tid & 127;
        const int q = tid >> 7;
        float w0 = W1[d], w1 = W1[HH + d], w2 = W1[2 * HH + d];
        const int i0 = q * 16;
#pragma unroll
        for (int r = 0; r < 16; r++) {
            int i = i0 + r;
            sWh[i * STR + d] = fmaf(sU[i * 3], w0, fmaf(sU[i * 3 + 1], w1, sU[i * 3 + 2] * w2));
        }
    }
    __syncthreads();

    // ---- P2: softmax layer 1
    softmax64_w8(sAt, sSi, sSj, tid);
    __syncthreads();

    // ---- P3: h = elu(attn1 @ Wh1), K=64, 64x8 warp tile
    {
        float acc0[8], acc1[8];
#pragma unroll
        for (int r = 0; r < 8; r++) { acc0[r] = 0.f; acc1[r] = 0.f; }
        for (int k0 = 0; k0 < MM; k0 += 4) {
            float2 w0 = *(const float2*)&sWh[(k0 + 0) * STR + c0];
            float2 w1 = *(const float2*)&sWh[(k0 + 1) * STR + c0];
            float2 w2 = *(const float2*)&sWh[(k0 + 2) * STR + c0];
            float2 w3 = *(const float2*)&sWh[(k0 + 3) * STR + c0];
#pragma unroll
            for (int r = 0; r < 8; r++) {
                int row = rg8 + r * 8;
                float4 a4 = *(const float4*)&sAt[row * AA + k0];
                acc0[r] = fmaf(a4.x, w0.x, acc0[r]);
                acc1[r] = fmaf(a4.x, w0.y, acc1[r]);
                acc0[r] = fmaf(a4.y, w1.x, acc0[r]);
                acc1[r] = fmaf(a4.y, w1.y, acc1[r]);
                acc0[r] = fmaf(a4.z, w2.x, acc0[r]);
                acc1[r] = fmaf(a4.z, w2.y, acc1[r]);
                acc0[r] = fmaf(a4.w, w3.x, acc0[r]);
                acc1[r] = fmaf(a4.w, w3.y, acc1[r]);
            }
        }
#pragma unroll
        for (int r = 0; r < 8; r++) {
            int row = rg8 + r * 8;
            float2 v;
            v.x = elu1(acc0[r]);
            v.y = elu1(acc1[r]);
            *(float2*)&sH[row * STR + c0] = v;
        }
    }
    __syncthreads();

    // ---- P4: layer2 si/sj = h @ c2 (64 rows x 8 lanes)
    {
        int row = tid >> 3, l8 = tid & 7;
        const float* hr = sH + row * STR + l8 * 16;
        const float* cl = sC2l + l8 * 16;
        const float* cr = sC2r + l8 * 16;
        float s1 = 0.f, s2 = 0.f;
#pragma unroll
        for (int k = 0; k < 16; k++) {
            float hv = hr[k];
            s1 = fmaf(hv, cl[k], s1);
            s2 = fmaf(hv, cr[k], s2);
        }
        s1 += __shfl_xor_sync(0xffffffffu, s1, 1);
        s2 += __shfl_xor_sync(0xffffffffu, s2, 1);
        s1 += __shfl_xor_sync(0xffffffffu, s1, 2);
        s2 += __shfl_xor_sync(0xffffffffu, s2, 2);
        s1 += __shfl_xor_sync(0xffffffffu, s1, 4);
        s2 += __shfl_xor_sync(0xffffffffu, s2, 4);
        if (!l8) { sSi[row] = s1; sSj[row] = s2; }
    }
    // ---- P5: Wh2 = h @ W2, K=128, cols from global
    {
        float acc0[8], acc1[8];
#pragma unroll
        for (int r = 0; r < 8; r++) { acc0[r] = 0.f; acc1[r] = 0.f; }
        for (int k0 = 0; k0 < HH; k0 += 4) {
            float2 w0 = *(const float2*)&W2[(k0 + 0) * HH + c0];
            float2 w1 = *(const float2*)&W2[(k0 + 1) * HH + c0];
            float2 w2 = *(const float2*)&W2[(k0 + 2) * HH + c0];
            float2 w3 = *(const float2*)&W2[(k0 + 3) * HH + c0];
#pragma unroll
            for (int r = 0; r < 8; r++) {
                int row = rg8 + r * 8;
                float4 h4 = *(const float4*)&sH[row * STR + k0];
                acc0[r] = fmaf(h4.x, w0.x, acc0[r]);
                acc1[r] = fmaf(h4.x, w0.y, acc1[r]);
                acc0[r] = fmaf(h4.y, w1.x, acc0[r]);
                acc1[r] = fmaf(h4.y, w1.y, acc1[r]);
                acc0[r] = fmaf(h4.z, w2.x, acc0[r]);
                acc1[r] = fmaf(h4.z, w2.y, acc1[r]);
                acc0[r] = fmaf(h4.w, w3.x, acc0[r]);
                acc1[r] = fmaf(h4.w, w3.y, acc1[r]);
            }
        }
        __syncthreads();   // sSi/sSj writes (P4) done; safe to overwrite sWh
#pragma unroll
        for (int r = 0; r < 8; r++) {
            int row = rg8 + r * 8;
            float2 v; v.x = acc0[r]; v.y = acc1[r];
            *(float2*)&sWh[row * STR + c0] = v;
        }
    }
    __syncthreads();

    // ---- P6: softmax layer 2
    softmax64_w8(sAt, sSi, sSj, tid);
    __syncthreads();

    // ---- P7: h2 = elu(attn2 @ Wh2) fused with max-pool (warp owns its 8 cols fully)
    {
        float acc0[8], acc1[8];
#pragma unroll
        for (int r = 0; r < 8; r++) { acc0[r] = 0.f; acc1[r] = 0.f; }
        for (int k0 = 0; k0 < MM; k0 += 4) {
            float2 w0 = *(const float2*)&sWh[(k0 + 0) * STR + c0];
            float2 w1 = *(const float2*)&sWh[(k0 + 1) * STR + c0];
            float2 w2 = *(const float2*)&sWh[(k0 + 2) * STR + c0];
            float2 w3 = *(const float2*)&sWh[(k0 + 3) * STR + c0];
#pragma unroll
            for (int r = 0; r < 8; r++) {
                int row = rg8 + r * 8;
                float4 a4 = *(const float4*)&sAt[row * AA + k0];
                acc0[r] = fmaf(a4.x, w0.x, acc0[r]);
                acc1[r] = fmaf(a4.x, w0.y, acc1[r]);
                acc0[r] = fmaf(a4.y, w1.x, acc0[r]);
                acc1[r] = fmaf(a4.y, w1.y, acc1[r]);
                acc0[r] = fmaf(a4.z, w2.x, acc0[r]);
                acc1[r] = fmaf(a4.z, w2.y, acc1[r]);
                acc0[r] = fmaf(a4.w, w3.x, acc0[r]);
                acc1[r] = fmaf(a4.w, w3.y, acc1[r]);
            }
        }
        float p0 = -1e30f, p1 = -1e30f;
#pragma unroll
        for (int r = 0; r < 8; r++) {
            p0 = fmaxf(p0, elu1(acc0[r]));
            p1 = fmaxf(p1, elu1(acc1[r]));
        }
        // reduce over the 8 row sub-groups (lane bits [2:5))
        p0 = fmaxf(p0, __shfl_xor_sync(0xffffffffu, p0, 4));
        p1 = fmaxf(p1, __shfl_xor_sync(0xffffffffu, p1, 4));
        p0 = fmaxf(p0, __shfl_xor_sync(0xffffffffu, p0, 8));
        p1 = fmaxf(p1, __shfl_xor_sync(0xffffffffu, p1, 8));
        p0 = fmaxf(p0, __shfl_xor_sync(0xffffffffu, p0, 16));
        p1 = fmaxf(p1, __shfl_xor_sync(0xffffffffu, p1, 16));
        if (rg8 == 0) {
            sPool[c0]     = p0;
            sPool[c0 + 1] = p1;
        }
    }
    __syncthreads();

    // ---- P8: hidden = relu(pooled @ mw1 + mb1)  (32 cols x 8 lanes)
    if (tid < 256) {
        int col = tid >> 3, l8 = tid & 7;
        float acc = 0.f;
        const float* pp = sPool + l8 * 16;
#pragma unroll
        for (int k = 0; k < 16; k++) acc = fmaf(pp[k], mw1[(l8 * 16 + k) * 32 + col], acc);
        acc += __shfl_xor_sync(0xffffffffu, acc, 1);
        acc += __shfl_xor_sync(0xffffffffu, acc, 2);
        acc += __shfl_xor_sync(0xffffffffu, acc, 4);
        if (!l8) sR[col] = fmaxf(acc + mb1[col], 0.f);
    }
    __syncthreads();

    // ---- P9: readout = hidden @ mw2 + mb2; relu + eps
    if (tid < 128) {
        float acc = mb2[tid];
#pragma unroll
        for (int m = 0; m < 32; m++) acc = fmaf(sR[m], mw2[m * HH + tid], acc);
        sO[tid] = fmaxf(acc, 0.f) + 1e-6f;
    }
    __syncthreads();

    // ---- P10: sums (delta = first 64, power = last 64)
    if (tid < 2) {
        float s = 0.f;
        const float* p = sO + tid * 64;
#pragma unroll 8
        for (int j = 0; j < 64; j++) s += p[j];
        sSum[tid] = s;
    }
    __syncthreads();

    // ---- P11: normalize & write. Output layout: power[B,A] then delta[B,A]
    if (tid < 128) {
        const float Bmax = 2.0f * 50.0f - 63.0f * 0.025f;  // 98.425
        const float PMAX = 1.0f;                            // 10^(30/10-3)
        if (tid < 64) {
            out[(size_t)B * AA + (size_t)b * AA + tid] = Bmax * sO[tid] / (sSum[0] + 1e-6f);
        } else {
            out[(size_t)b * AA + (tid - 64)] = PMAX * sO[tid] / (sSum[1] + 1e-6f);
        }
    }
}

static const int SMEM_FLOATS = 2 * MM * STR + MM * AA + 192 + 64 + 64 + 128 + 128 + 128 + 32 + 128 + 2;

extern "C" void kernel_launch(void* const* d_in, const int* in_sizes, int n_in,
                              void* d_out, int out_size) {
    const float* users = (const float*)d_in[0];
    const float* W1    = (const float*)d_in[1];
    const float* a1    = (const float*)d_in[2];
    const float* W2    = (const float*)d_in[3];
    const float* a2    = (const float*)d_in[4];
    const float* mw1   = (const float*)d_in[5];
    const float* mb1   = (const float*)d_in[6];
    const float* mw2   = (const float*)d_in[7];
    const float* mb2   = (const float*)d_in[8];
    float* out = (float*)d_out;

    int B = in_sizes[0] / (MM * INF_);
    size_t smem = (size_t)SMEM_FLOATS * sizeof(float);

    cudaFuncSetAttribute(gat_kernel, cudaFuncAttributeMaxDynamicSharedMemorySize, (int)smem);

    precomp_kernel<<<1, 128>>>(W1, a1, W2, a2);
    gat_kernel<<<B, NT, smem>>>(users, W1, W2, mw1, mb1, mw2, mb2, out, B);
}

// round 5
// speedup vs baseline: 1.6906x; 1.4961x over previous
#include <cuda_runtime.h>

#define MM   64      // nodes per graph
#define HH   128     // hidden
#define INF_ 3       // input feats
#define AA   64      // A
#define STR  132     // padded row stride for 64x128 tiles (floats)
#define ASTR 68      // padded row stride for attn 64x64 tile (floats) — 272B % 128B = 16
#define NT   512     // threads per CTA

__device__ float g_c2l[HH], g_c2r[HH], g_c1l[INF_], g_c1r[INF_];

__global__ void precomp_kernel(const float* __restrict__ W1, const float* __restrict__ a1,
                               const float* __restrict__ W2, const float* __restrict__ a2) {
    int t = threadIdx.x;  // 128 threads
    float s1 = 0.f, s2 = 0.f;
#pragma unroll 8
    for (int j = 0; j < HH; j++) {
        float w = W2[t * HH + j];
        s1 = fmaf(w, a2[j], s1);
        s2 = fmaf(w, a2[HH + j], s2);
    }
    g_c2l[t] = s1;
    g_c2r[t] = s2;
    if (t < INF_) {
        float p = 0.f, q = 0.f;
#pragma unroll 8
        for (int j = 0; j < HH; j++) {
            float w = W1[t * HH + j];
            p = fmaf(w, a1[j], p);
            q = fmaf(w, a1[HH + j], q);
        }
        g_c1l[t] = p;
        g_c1r[t] = q;
    }
}

// Softmax over 64 cols, 8 lanes per row (512 threads -> 64 rows x 8 lanes).
__device__ __forceinline__ void softmax64_w8(float* __restrict__ sAt,
                                             const float* __restrict__ sSi,
                                             const float* __restrict__ sSj, int tid) {
    int row = tid >> 3, lane = tid & 7;
    float si = sSi[row];
    const float* sj = sSj + lane * 8;
    float ev[8];
    float m = -1e30f;
#pragma unroll
    for (int j = 0; j < 8; j++) {
        float x = si + sj[j];
        x = (x > 0.f) ? x : 0.2f * x;  // leaky_relu alpha=0.2
        ev[j] = x;
        m = fmaxf(m, x);
    }
    m = fmaxf(m, __shfl_xor_sync(0xffffffffu, m, 1));
    m = fmaxf(m, __shfl_xor_sync(0xffffffffu, m, 2));
    m = fmaxf(m, __shfl_xor_sync(0xffffffffu, m, 4));
    float s = 0.f;
#pragma unroll
    for (int j = 0; j < 8; j++) {
        float e = __expf(ev[j] - m);
        ev[j] = e;
        s += e;
    }
    s += __shfl_xor_sync(0xffffffffu, s, 1);
    s += __shfl_xor_sync(0xffffffffu, s, 2);
    s += __shfl_xor_sync(0xffffffffu, s, 4);
    float inv = 1.0f / s;
    float* dst = sAt + row * ASTR + lane * 8;
#pragma unroll
    for (int j = 0; j < 8; j++) dst[j] = ev[j] * inv;
}

__device__ __forceinline__ float elu1(float x) {
    return (x > 0.f) ? x : (__expf(x) - 1.0f);
}

__global__ __launch_bounds__(NT, 2) void gat_kernel(
    const float* __restrict__ users, const float* __restrict__ W1,
    const float* __restrict__ W2,
    const float* __restrict__ mw1, const float* __restrict__ mb1,
    const float* __restrict__ mw2, const float* __restrict__ mb2,
    float* __restrict__ out, int B) {
    extern __shared__ float sm[];
    float* sWh   = sm;                    // 64*132
    float* sH    = sWh + MM * STR;        // 64*132
    float* sAt   = sH + MM * STR;         // 64*68 (padded stride)
    float* sU    = sAt + MM * ASTR;       // 192
    float* sSi   = sU + 192;              // 64
    float* sSj   = sSi + 64;              // 64
    float* sC2l  = sSj + 64;              // 128
    float* sC2r  = sC2l + 128;            // 128
    float* sPool = sC2r + 128;            // 128
    float* sR    = sPool + 128;           // 32
    float* sO    = sR + 32;               // 128
    float* sSum  = sO + 128;              // 2

    const int tid  = threadIdx.x;
    const int b    = blockIdx.x;
    // GEMM decomposition: warp tile = 64 rows x 8 cols; thread = 8 rows x 2 cols
    const int warp = tid >> 5;           // 16 warps -> col octet
    const int lane = tid & 31;
    const int rg8  = lane >> 2;          // 0..7 row sub-group (rows rg8, rg8+8, ...)
    const int cp   = lane & 3;           // 0..3 col pair
    const int c0   = warp * 8 + cp * 2;  // first of 2 columns

    // ---- P0: load users + c2 vectors
    if (tid < MM * INF_) sU[tid] = users[b * (MM * INF_) + tid];
    if (tid < 128) { sC2l[tid] = g_c2l[tid]; sC2r[tid] = g_c2r[tid]; }
    __syncthreads();

    // ---- P1: layer1 si/sj via c1 trick
    if (tid < MM) {
        float u0 = sU[tid * 3], u1 = sU[tid * 3 + 1], u2 = sU[tid * 3 + 2];
        sSi[tid] = u0 * g_c1l[0] + u1 * g_c1l[1] + u2 * g_c1l[2];
        sSj[tid] = u0 * g_c1r[0] + u1 * g_c1r[1] + u2 * g_c1r[2];
    }
    // ---- P1b: Wh1 = users @ W1 (thread = (quarter, column))
    {
        const int d = tid & 127;
        const int q = tid >> 7;
        float w0 = W1[d], w1 = W1[HH + d], w2 = W1[2 * HH + d];
        const int i0 = q * 16;
#pragma unroll
        for (int r = 0; r < 16; r++) {
            int i = i0 + r;
            sWh[i * STR + d] = fmaf(sU[i * 3], w0, fmaf(sU[i * 3 + 1], w1, sU[i * 3 + 2] * w2));
        }
    }
    __syncthreads();

    // ---- P2: softmax layer 1
    softmax64_w8(sAt, sSi, sSj, tid);
    __syncthreads();

    // ---- P3: h = elu(attn1 @ Wh1), K=64, 64x8 warp tile
    {
        float acc0[8], acc1[8];
#pragma unroll
        for (int r = 0; r < 8; r++) { acc0[r] = 0.f; acc1[r] = 0.f; }
        for (int k0 = 0; k0 < MM; k0 += 4) {
            float2 w0 = *(const float2*)&sWh[(k0 + 0) * STR + c0];
            float2 w1 = *(const float2*)&sWh[(k0 + 1) * STR + c0];
            float2 w2 = *(const float2*)&sWh[(k0 + 2) * STR + c0];
            float2 w3 = *(const float2*)&sWh[(k0 + 3) * STR + c0];
#pragma unroll
            for (int r = 0; r < 8; r++) {
                int row = rg8 + r * 8;
                float4 a4 = *(const float4*)&sAt[row * ASTR + k0];
                acc0[r] = fmaf(a4.x, w0.x, acc0[r]);
                acc1[r] = fmaf(a4.x, w0.y, acc1[r]);
                acc0[r] = fmaf(a4.y, w1.x, acc0[r]);
                acc1[r] = fmaf(a4.y, w1.y, acc1[r]);
                acc0[r] = fmaf(a4.z, w2.x, acc0[r]);
                acc1[r] = fmaf(a4.z, w2.y, acc1[r]);
                acc0[r] = fmaf(a4.w, w3.x, acc0[r]);
                acc1[r] = fmaf(a4.w, w3.y, acc1[r]);
            }
        }
#pragma unroll
        for (int r = 0; r < 8; r++) {
            int row = rg8 + r * 8;
            float2 v;
            v.x = elu1(acc0[r]);
            v.y = elu1(acc1[r]);
            *(float2*)&sH[row * STR + c0] = v;
        }
    }
    __syncthreads();

    // ---- P4: layer2 si/sj = h @ c2 (64 rows x 8 lanes)
    {
        int row = tid >> 3, l8 = tid & 7;
        const float* hr = sH + row * STR + l8 * 16;
        const float* cl = sC2l + l8 * 16;
        const float* cr = sC2r + l8 * 16;
        float s1 = 0.f, s2 = 0.f;
#pragma unroll
        for (int k = 0; k < 16; k++) {
            float hv = hr[k];
            s1 = fmaf(hv, cl[k], s1);
            s2 = fmaf(hv, cr[k], s2);
        }
        s1 += __shfl_xor_sync(0xffffffffu, s1, 1);
        s2 += __shfl_xor_sync(0xffffffffu, s2, 1);
        s1 += __shfl_xor_sync(0xffffffffu, s1, 2);
        s2 += __shfl_xor_sync(0xffffffffu, s2, 2);
        s1 += __shfl_xor_sync(0xffffffffu, s1, 4);
        s2 += __shfl_xor_sync(0xffffffffu, s2, 4);
        if (!l8) { sSi[row] = s1; sSj[row] = s2; }
    }
    // ---- P5: Wh2 = h @ W2, K=128, cols from global
    {
        float acc0[8], acc1[8];
#pragma unroll
        for (int r = 0; r < 8; r++) { acc0[r] = 0.f; acc1[r] = 0.f; }
        for (int k0 = 0; k0 < HH; k0 += 4) {
            float2 w0 = *(const float2*)&W2[(k0 + 0) * HH + c0];
            float2 w1 = *(const float2*)&W2[(k0 + 1) * HH + c0];
            float2 w2 = *(const float2*)&W2[(k0 + 2) * HH + c0];
            float2 w3 = *(const float2*)&W2[(k0 + 3) * HH + c0];
#pragma unroll
            for (int r = 0; r < 8; r++) {
                int row = rg8 + r * 8;
                float4 h4 = *(const float4*)&sH[row * STR + k0];
                acc0[r] = fmaf(h4.x, w0.x, acc0[r]);
                acc1[r] = fmaf(h4.x, w0.y, acc1[r]);
                acc0[r] = fmaf(h4.y, w1.x, acc0[r]);
                acc1[r] = fmaf(h4.y, w1.y, acc1[r]);
                acc0[r] = fmaf(h4.z, w2.x, acc0[r]);
                acc1[r] = fmaf(h4.z, w2.y, acc1[r]);
                acc0[r] = fmaf(h4.w, w3.x, acc0[r]);
                acc1[r] = fmaf(h4.w, w3.y, acc1[r]);
            }
        }
        __syncthreads();   // sSi/sSj writes (P4) done; safe to overwrite sWh
#pragma unroll
        for (int r = 0; r < 8; r++) {
            int row = rg8 + r * 8;
            float2 v; v.x = acc0[r]; v.y = acc1[r];
            *(float2*)&sWh[row * STR + c0] = v;
        }
    }
    __syncthreads();

    // ---- P6: softmax layer 2
    softmax64_w8(sAt, sSi, sSj, tid);
    __syncthreads();

    // ---- P7: h2 = elu(attn2 @ Wh2) fused with max-pool (warp owns its 8 cols fully)
    {
        float acc0[8], acc1[8];
#pragma unroll
        for (int r = 0; r < 8; r++) { acc0[r] = 0.f; acc1[r] = 0.f; }
        for (int k0 = 0; k0 < MM; k0 += 4) {
            float2 w0 = *(const float2*)&sWh[(k0 + 0) * STR + c0];
            float2 w1 = *(const float2*)&sWh[(k0 + 1) * STR + c0];
            float2 w2 = *(const float2*)&sWh[(k0 + 2) * STR + c0];
            float2 w3 = *(const float2*)&sWh[(k0 + 3) * STR + c0];
#pragma unroll
            for (int r = 0; r < 8; r++) {
                int row = rg8 + r * 8;
                float4 a4 = *(const float4*)&sAt[row * ASTR + k0];
                acc0[r] = fmaf(a4.x, w0.x, acc0[r]);
                acc1[r] = fmaf(a4.x, w0.y, acc1[r]);
                acc0[r] = fmaf(a4.y, w1.x, acc0[r]);
                acc1[r] = fmaf(a4.y, w1.y, acc1[r]);
                acc0[r] = fmaf(a4.z, w2.x, acc0[r]);
                acc1[r] = fmaf(a4.z, w2.y, acc1[r]);
                acc0[r] = fmaf(a4.w, w3.x, acc0[r]);
                acc1[r] = fmaf(a4.w, w3.y, acc1[r]);
            }
        }
        float p0 = -1e30f, p1 = -1e30f;
#pragma unroll
        for (int r = 0; r < 8; r++) {
            p0 = fmaxf(p0, elu1(acc0[r]));
            p1 = fmaxf(p1, elu1(acc1[r]));
        }
        // reduce over the 8 row sub-groups (lane bits [2:5))
        p0 = fmaxf(p0, __shfl_xor_sync(0xffffffffu, p0, 4));
        p1 = fmaxf(p1, __shfl_xor_sync(0xffffffffu, p1, 4));
        p0 = fmaxf(p0, __shfl_xor_sync(0xffffffffu, p0, 8));
        p1 = fmaxf(p1, __shfl_xor_sync(0xffffffffu, p1, 8));
        p0 = fmaxf(p0, __shfl_xor_sync(0xffffffffu, p0, 16));
        p1 = fmaxf(p1, __shfl_xor_sync(0xffffffffu, p1, 16));
        if (rg8 == 0) {
            sPool[c0]     = p0;
            sPool[c0 + 1] = p1;
        }
    }
    __syncthreads();

    // ---- P8: hidden = relu(pooled @ mw1 + mb1)  (32 cols x 8 lanes)
    if (tid < 256) {
        int col = tid >> 3, l8 = tid & 7;
        float acc = 0.f;
        const float* pp = sPool + l8 * 16;
#pragma unroll
        for (int k = 0; k < 16; k++) acc = fmaf(pp[k], mw1[(l8 * 16 + k) * 32 + col], acc);
        acc += __shfl_xor_sync(0xffffffffu, acc, 1);
        acc += __shfl_xor_sync(0xffffffffu, acc, 2);
        acc += __shfl_xor_sync(0xffffffffu, acc, 4);
        if (!l8) sR[col] = fmaxf(acc + mb1[col], 0.f);
    }
    __syncthreads();

    // ---- P9: readout = hidden @ mw2 + mb2; relu + eps
    if (tid < 128) {
        float acc = mb2[tid];
#pragma unroll
        for (int m = 0; m < 32; m++) acc = fmaf(sR[m], mw2[m * HH + tid], acc);
        sO[tid] = fmaxf(acc, 0.f) + 1e-6f;
    }
    __syncthreads();

    // ---- P10: sums (delta = first 64, power = last 64)
    if (tid < 2) {
        float s = 0.f;
        const float* p = sO + tid * 64;
#pragma unroll 8
        for (int j = 0; j < 64; j++) s += p[j];
        sSum[tid] = s;
    }
    __syncthreads();

    // ---- P11: normalize & write. Output layout: power[B,A] then delta[B,A]
    if (tid < 128) {
        const float Bmax = 2.0f * 50.0f - 63.0f * 0.025f;  // 98.425
        const float PMAX = 1.0f;                            // 10^(30/10-3)
        if (tid < 64) {
            out[(size_t)B * AA + (size_t)b * AA + tid] = Bmax * sO[tid] / (sSum[0] + 1e-6f);
        } else {
            out[(size_t)b * AA + (tid - 64)] = PMAX * sO[tid] / (sSum[1] + 1e-6f);
        }
    }
}

static const int SMEM_FLOATS = 2 * MM * STR + MM * ASTR + 192 + 64 + 64 + 128 + 128 + 128 + 32 + 128 + 2;

extern "C" void kernel_launch(void* const* d_in, const int* in_sizes, int n_in,
                              void* d_out, int out_size) {
    const float* users = (const float*)d_in[0];
    const float* W1    = (const float*)d_in[1];
    const float* a1    = (const float*)d_in[2];
    const float* W2    = (const float*)d_in[3];
    const float* a2    = (const float*)d_in[4];
    const float* mw1   = (const float*)d_in[5];
    const float* mb1   = (const float*)d_in[6];
    const float* mw2   = (const float*)d_in[7];
    const float* mb2   = (const float*)d_in[8];
    float* out = (float*)d_out;

    int B = in_sizes[0] / (MM * INF_);
    size_t smem = (size_t)SMEM_FLOATS * sizeof(float);

    cudaFuncSetAttribute(gat_kernel, cudaFuncAttributeMaxDynamicSharedMemorySize, (int)smem);

    precomp_kernel<<<1, 128>>>(W1, a1, W2, a2);
    gat_kernel<<<B, NT, smem>>>(users, W1, W2, mw1, mb1, mw2, mb2, out, B);
}

// round 6
// speedup vs baseline: 1.7033x; 1.0075x over previous
#include <cuda_runtime.h>

#define MM   64      // nodes per graph
#define HH   128     // hidden
#define INF_ 3       // input feats
#define AA   64      // A
#define STR  132     // padded row stride for 64x128 tiles (floats)
#define ASTR 68      // padded row stride for attn 64x64 tile (floats) — 272B % 128B = 16
#define NT   512     // threads per CTA

__device__ float g_c2l[HH], g_c2r[HH], g_c1l[INF_], g_c1r[INF_];

__global__ void precomp_kernel(const float* __restrict__ W1, const float* __restrict__ a1,
                               const float* __restrict__ W2, const float* __restrict__ a2) {
    int t = threadIdx.x;  // 128 threads
    float s1 = 0.f, s2 = 0.f;
#pragma unroll 8
    for (int j = 0; j < HH; j++) {
        float w = W2[t * HH + j];
        s1 = fmaf(w, a2[j], s1);
        s2 = fmaf(w, a2[HH + j], s2);
    }
    g_c2l[t] = s1;
    g_c2r[t] = s2;
    if (t < INF_) {
        float p = 0.f, q = 0.f;
#pragma unroll 8
        for (int j = 0; j < HH; j++) {
            float w = W1[t * HH + j];
            p = fmaf(w, a1[j], p);
            q = fmaf(w, a1[HH + j], q);
        }
        g_c1l[t] = p;
        g_c1r[t] = q;
    }
}

// Softmax over 64 cols, 8 lanes per row (512 threads -> 64 rows x 8 lanes).
__device__ __forceinline__ void softmax64_w8(float* __restrict__ sAt,
                                             const float* __restrict__ sSi,
                                             const float* __restrict__ sSj, int tid) {
    int row = tid >> 3, lane = tid & 7;
    float si = sSi[row];
    const float* sj = sSj + lane * 8;
    float ev[8];
    float m = -1e30f;
#pragma unroll
    for (int j = 0; j < 8; j++) {
        float x = si + sj[j];
        x = (x > 0.f) ? x : 0.2f * x;  // leaky_relu alpha=0.2
        ev[j] = x;
        m = fmaxf(m, x);
    }
    m = fmaxf(m, __shfl_xor_sync(0xffffffffu, m, 1));
    m = fmaxf(m, __shfl_xor_sync(0xffffffffu, m, 2));
    m = fmaxf(m, __shfl_xor_sync(0xffffffffu, m, 4));
    float s = 0.f;
#pragma unroll
    for (int j = 0; j < 8; j++) {
        float e = __expf(ev[j] - m);
        ev[j] = e;
        s += e;
    }
    s += __shfl_xor_sync(0xffffffffu, s, 1);
    s += __shfl_xor_sync(0xffffffffu, s, 2);
    s += __shfl_xor_sync(0xffffffffu, s, 4);
    float inv = 1.0f / s;
    float* dst = sAt + row * ASTR + lane * 8;
#pragma unroll
    for (int j = 0; j < 8; j++) dst[j] = ev[j] * inv;
}

__device__ __forceinline__ float elu1(float x) {
    return (x > 0.f) ? x : (__expf(x) - 1.0f);
}

__global__ __launch_bounds__(NT, 2) void gat_kernel(
    const float* __restrict__ users, const float* __restrict__ W1,
    const float* __restrict__ W2,
    const float* __restrict__ mw1, const float* __restrict__ mb1,
    const float* __restrict__ mw2, const float* __restrict__ mb2,
    float* __restrict__ out, int B) {
    extern __shared__ float sm[];
    float* sWh   = sm;                    // 64*132
    float* sH    = sWh + MM * STR;        // 64*132
    float* sAt   = sH + MM * STR;         // 64*68
    float* sU    = sAt + MM * ASTR;       // 192
    float* sSi   = sU + 192;              // 64
    float* sSj   = sSi + 64;              // 64
    float* sC2l  = sSj + 64;              // 128
    float* sC2r  = sC2l + 128;            // 128
    float* sPoolH= sC2r + 128;            // 256 (2 halves x 128)
    float* sPool = sPoolH + 256;          // 128
    float* sR    = sPool + 128;           // 32
    float* sO    = sR + 32;               // 128
    float* sSum  = sO + 128;              // 2

    const int tid  = threadIdx.x;
    const int b    = blockIdx.x;
    // GEMM decomposition: warp tile = 32 rows x 16 cols; thread = 4 rows x 4 cols
    const int warp  = tid >> 5;
    const int lane  = tid & 31;
    const int rh    = warp >> 3;          // row half: rows rh*32 .. rh*32+31
    const int octet = warp & 7;           // col octet (16 cols)
    const int rg    = lane >> 2;          // 0..7 row sub-group
    const int cp    = lane & 3;           // 0..3 col quad
    const int c0    = octet * 16 + cp * 4;
    const int r0    = rh * 32 + rg;       // rows r0 + 8*j, j=0..3

    // ---- P0: load users + c2 vectors
    if (tid < MM * INF_) sU[tid] = users[b * (MM * INF_) + tid];
    if (tid < 128) { sC2l[tid] = g_c2l[tid]; sC2r[tid] = g_c2r[tid]; }
    __syncthreads();

    // ---- P1: layer1 si/sj via c1 trick
    if (tid < MM) {
        float u0 = sU[tid * 3], u1 = sU[tid * 3 + 1], u2 = sU[tid * 3 + 2];
        sSi[tid] = u0 * g_c1l[0] + u1 * g_c1l[1] + u2 * g_c1l[2];
        sSj[tid] = u0 * g_c1r[0] + u1 * g_c1r[1] + u2 * g_c1r[2];
    }
    // ---- P1b: Wh1 = users @ W1 (thread = (quarter, column))
    {
        const int d = tid & 127;
        const int q = tid >> 7;
        float w0 = W1[d], w1 = W1[HH + d], w2 = W1[2 * HH + d];
        const int i0 = q * 16;
#pragma unroll
        for (int r = 0; r < 16; r++) {
            int i = i0 + r;
            sWh[i * STR + d] = fmaf(sU[i * 3], w0, fmaf(sU[i * 3 + 1], w1, sU[i * 3 + 2] * w2));
        }
    }
    __syncthreads();

    // ---- P2: softmax layer 1
    softmax64_w8(sAt, sSi, sSj, tid);
    __syncthreads();

    // ---- P3: h = elu(attn1 @ Wh1), K=64, thread tile 4 rows x 4 cols
    {
        float4 acc[4];
#pragma unroll
        for (int j = 0; j < 4; j++) acc[j] = make_float4(0.f, 0.f, 0.f, 0.f);
        for (int k0 = 0; k0 < MM; k0 += 4) {
            float4 w0 = *(const float4*)&sWh[(k0 + 0) * STR + c0];
            float4 w1 = *(const float4*)&sWh[(k0 + 1) * STR + c0];
            float4 w2 = *(const float4*)&sWh[(k0 + 2) * STR + c0];
            float4 w3 = *(const float4*)&sWh[(k0 + 3) * STR + c0];
#pragma unroll
            for (int j = 0; j < 4; j++) {
                float4 a4 = *(const float4*)&sAt[(r0 + 8 * j) * ASTR + k0];
                acc[j].x = fmaf(a4.x, w0.x, acc[j].x);
                acc[j].y = fmaf(a4.x, w0.y, acc[j].y);
                acc[j].z = fmaf(a4.x, w0.z, acc[j].z);
                acc[j].w = fmaf(a4.x, w0.w, acc[j].w);
                acc[j].x = fmaf(a4.y, w1.x, acc[j].x);
                acc[j].y = fmaf(a4.y, w1.y, acc[j].y);
                acc[j].z = fmaf(a4.y, w1.z, acc[j].z);
                acc[j].w = fmaf(a4.y, w1.w, acc[j].w);
                acc[j].x = fmaf(a4.z, w2.x, acc[j].x);
                acc[j].y = fmaf(a4.z, w2.y, acc[j].y);
                acc[j].z = fmaf(a4.z, w2.z, acc[j].z);
                acc[j].w = fmaf(a4.z, w2.w, acc[j].w);
                acc[j].x = fmaf(a4.w, w3.x, acc[j].x);
                acc[j].y = fmaf(a4.w, w3.y, acc[j].y);
                acc[j].z = fmaf(a4.w, w3.z, acc[j].z);
                acc[j].w = fmaf(a4.w, w3.w, acc[j].w);
            }
        }
#pragma unroll
        for (int j = 0; j < 4; j++) {
            float4 v;
            v.x = elu1(acc[j].x);
            v.y = elu1(acc[j].y);
            v.z = elu1(acc[j].z);
            v.w = elu1(acc[j].w);
            *(float4*)&sH[(r0 + 8 * j) * STR + c0] = v;
        }
    }
    __syncthreads();

    // ---- P4: layer2 si/sj = h @ c2 (64 rows x 8 lanes)
    {
        int row = tid >> 3, l8 = tid & 7;
        const float* hr = sH + row * STR + l8 * 16;
        const float* cl = sC2l + l8 * 16;
        const float* cr = sC2r + l8 * 16;
        float s1 = 0.f, s2 = 0.f;
#pragma unroll
        for (int k = 0; k < 16; k++) {
            float hv = hr[k];
            s1 = fmaf(hv, cl[k], s1);
            s2 = fmaf(hv, cr[k], s2);
        }
        s1 += __shfl_xor_sync(0xffffffffu, s1, 1);
        s2 += __shfl_xor_sync(0xffffffffu, s2, 1);
        s1 += __shfl_xor_sync(0xffffffffu, s1, 2);
        s2 += __shfl_xor_sync(0xffffffffu, s2, 2);
        s1 += __shfl_xor_sync(0xffffffffu, s1, 4);
        s2 += __shfl_xor_sync(0xffffffffu, s2, 4);
        if (!l8) { sSi[row] = s1; sSj[row] = s2; }
    }
    // ---- P5: Wh2 = h @ W2, K=128, cols from global (L1/L2 cached)
    {
        float4 acc[4];
#pragma unroll
        for (int j = 0; j < 4; j++) acc[j] = make_float4(0.f, 0.f, 0.f, 0.f);
        for (int k0 = 0; k0 < HH; k0 += 4) {
            float4 w0 = *(const float4*)&W2[(k0 + 0) * HH + c0];
            float4 w1 = *(const float4*)&W2[(k0 + 1) * HH + c0];
            float4 w2 = *(const float4*)&W2[(k0 + 2) * HH + c0];
            float4 w3 = *(const float4*)&W2[(k0 + 3) * HH + c0];
#pragma unroll
            for (int j = 0; j < 4; j++) {
                float4 h4 = *(const float4*)&sH[(r0 + 8 * j) * STR + k0];
                acc[j].x = fmaf(h4.x, w0.x, acc[j].x);
                acc[j].y = fmaf(h4.x, w0.y, acc[j].y);
                acc[j].z = fmaf(h4.x, w0.z, acc[j].z);
                acc[j].w = fmaf(h4.x, w0.w, acc[j].w);
                acc[j].x = fmaf(h4.y, w1.x, acc[j].x);
                acc[j].y = fmaf(h4.y, w1.y, acc[j].y);
                acc[j].z = fmaf(h4.y, w1.z, acc[j].z);
                acc[j].w = fmaf(h4.y, w1.w, acc[j].w);
                acc[j].x = fmaf(h4.z, w2.x, acc[j].x);
                acc[j].y = fmaf(h4.z, w2.y, acc[j].y);
                acc[j].z = fmaf(h4.z, w2.z, acc[j].z);
                acc[j].w = fmaf(h4.z, w2.w, acc[j].w);
                acc[j].x = fmaf(h4.w, w3.x, acc[j].x);
                acc[j].y = fmaf(h4.w, w3.y, acc[j].y);
                acc[j].z = fmaf(h4.w, w3.z, acc[j].z);
                acc[j].w = fmaf(h4.w, w3.w, acc[j].w);
            }
        }
#pragma unroll
        for (int j = 0; j < 4; j++)
            *(float4*)&sWh[(r0 + 8 * j) * STR + c0] = acc[j];
    }
    __syncthreads();

    // ---- P6: softmax layer 2
    softmax64_w8(sAt, sSi, sSj, tid);
    __syncthreads();

    // ---- P7: h2 = elu(attn2 @ Wh2) fused with max-pool
    {
        float4 acc[4];
#pragma unroll
        for (int j = 0; j < 4; j++) acc[j] = make_float4(0.f, 0.f, 0.f, 0.f);
        for (int k0 = 0; k0 < MM; k0 += 4) {
            float4 w0 = *(const float4*)&sWh[(k0 + 0) * STR + c0];
            float4 w1 = *(const float4*)&sWh[(k0 + 1) * STR + c0];
            float4 w2 = *(const float4*)&sWh[(k0 + 2) * STR + c0];
            float4 w3 = *(const float4*)&sWh[(k0 + 3) * STR + c0];
#pragma unroll
            for (int j = 0; j < 4; j++) {
                float4 a4 = *(const float4*)&sAt[(r0 + 8 * j) * ASTR + k0];
                acc[j].x = fmaf(a4.x, w0.x, acc[j].x);
                acc[j].y = fmaf(a4.x, w0.y, acc[j].y);
                acc[j].z = fmaf(a4.x, w0.z, acc[j].z);
                acc[j].w = fmaf(a4.x, w0.w, acc[j].w);
                acc[j].x = fmaf(a4.y, w1.x, acc[j].x);
                acc[j].y = fmaf(a4.y, w1.y, acc[j].y);
                acc[j].z = fmaf(a4.y, w1.z, acc[j].z);
                acc[j].w = fmaf(a4.y, w1.w, acc[j].w);
                acc[j].x = fmaf(a4.z, w2.x, acc[j].x);
                acc[j].y = fmaf(a4.z, w2.y, acc[j].y);
                acc[j].z = fmaf(a4.z, w2.z, acc[j].z);
                acc[j].w = fmaf(a4.z, w2.w, acc[j].w);
                acc[j].x = fmaf(a4.w, w3.x, acc[j].x);
                acc[j].y = fmaf(a4.w, w3.y, acc[j].y);
                acc[j].z = fmaf(a4.w, w3.z, acc[j].z);
                acc[j].w = fmaf(a4.w, w3.w, acc[j].w);
            }
        }
        float px = -1e30f, py = -1e30f, pz = -1e30f, pw = -1e30f;
#pragma unroll
        for (int j = 0; j < 4; j++) {
            px = fmaxf(px, elu1(acc[j].x));
            py = fmaxf(py, elu1(acc[j].y));
            pz = fmaxf(pz, elu1(acc[j].z));
            pw = fmaxf(pw, elu1(acc[j].w));
        }
        // reduce over the 8 row sub-groups (lane bits [2:5))
#pragma unroll
        for (int off = 4; off < 32; off <<= 1) {
            px = fmaxf(px, __shfl_xor_sync(0xffffffffu, px, off));
            py = fmaxf(py, __shfl_xor_sync(0xffffffffu, py, off));
            pz = fmaxf(pz, __shfl_xor_sync(0xffffffffu, pz, off));
            pw = fmaxf(pw, __shfl_xor_sync(0xffffffffu, pw, off));
        }
        if (rg == 0)
            *(float4*)&sPoolH[rh * 128 + c0] = make_float4(px, py, pz, pw);
    }
    __syncthreads();

    // ---- P7b: combine the two row halves
    if (tid < 128) sPool[tid] = fmaxf(sPoolH[tid], sPoolH[128 + tid]);
    __syncthreads();

    // ---- P8: hidden = relu(pooled @ mw1 + mb1)  (32 cols x 8 lanes)
    if (tid < 256) {
        int col = tid >> 3, l8 = tid & 7;
        float acc = 0.f;
        const float* pp = sPool + l8 * 16;
#pragma unroll
        for (int k = 0; k < 16; k++) acc = fmaf(pp[k], mw1[(l8 * 16 + k) * 32 + col], acc);
        acc += __shfl_xor_sync(0xffffffffu, acc, 1);
        acc += __shfl_xor_sync(0xffffffffu, acc, 2);
        acc += __shfl_xor_sync(0xffffffffu, acc, 4);
        if (!l8) sR[col] = fmaxf(acc + mb1[col], 0.f);
    }
    __syncthreads();

    // ---- P9: readout = hidden @ mw2 + mb2; relu + eps
    if (tid < 128) {
        float acc = mb2[tid];
#pragma unroll
        for (int m = 0; m < 32; m++) acc = fmaf(sR[m], mw2[m * HH + tid], acc);
        sO[tid] = fmaxf(acc, 0.f) + 1e-6f;
    }
    __syncthreads();

    // ---- P10: sums (delta = first 64, power = last 64)
    if (tid < 2) {
        float s = 0.f;
        const float* p = sO + tid * 64;
#pragma unroll 8
        for (int j = 0; j < 64; j++) s += p[j];
        sSum[tid] = s;
    }
    __syncthreads();

    // ---- P11: normalize & write. Output layout: power[B,A] then delta[B,A]
    if (tid < 128) {
        const float Bmax = 2.0f * 50.0f - 63.0f * 0.025f;  // 98.425
        const float PMAX = 1.0f;                            // 10^(30/10-3)
        if (tid < 64) {
            out[(size_t)B * AA + (size_t)b * AA + tid] = Bmax * sO[tid] / (sSum[0] + 1e-6f);
        } else {
            out[(size_t)b * AA + (tid - 64)] = PMAX * sO[tid] / (sSum[1] + 1e-6f);
        }
    }
}

static const int SMEM_FLOATS = 2 * MM * STR + MM * ASTR + 192 + 64 + 64 + 128 + 128 + 256 + 128 + 32 + 128 + 2;

extern "C" void kernel_launch(void* const* d_in, const int* in_sizes, int n_in,
                              void* d_out, int out_size) {
    const float* users = (const float*)d_in[0];
    const float* W1    = (const float*)d_in[1];
    const float* a1    = (const float*)d_in[2];
    const float* W2    = (const float*)d_in[3];
    const float* a2    = (const float*)d_in[4];
    const float* mw1   = (const float*)d_in[5];
    const float* mb1   = (const float*)d_in[6];
    const float* mw2   = (const float*)d_in[7];
    const float* mb2   = (const float*)d_in[8];
    float* out = (float*)d_out;

    int B = in_sizes[0] / (MM * INF_);
    size_t smem = (size_t)SMEM_FLOATS * sizeof(float);

    cudaFuncSetAttribute(gat_kernel, cudaFuncAttributeMaxDynamicSharedMemorySize, (int)smem);

    precomp_kernel<<<1, 128>>>(W1, a1, W2, a2);
    gat_kernel<<<B, NT, smem>>>(users, W1, W2, mw1, mb1, mw2, mb2, out, B);
}

// round 7
// speedup vs baseline: 2.0391x; 1.1972x over previous
#include <cuda_runtime.h>

#define MM   64      // nodes per graph
#define HH   128     // hidden
#define INF_ 3       // input feats
#define AA   64      // A
#define STR  132     // padded row stride for 64x128 tiles (floats)
#define ASTR 68      // padded row stride for attn 64x64 tile (floats) — 272B % 128B = 16
#define NT   512     // threads per CTA

__device__ float g_c2l[HH], g_c2r[HH], g_c1l[INF_], g_c1r[INF_];

__global__ void precomp_kernel(const float* __restrict__ W1, const float* __restrict__ a1,
                               const float* __restrict__ W2, const float* __restrict__ a2) {
    int t = threadIdx.x;  // 128 threads
    float s1 = 0.f, s2 = 0.f;
#pragma unroll 8
    for (int j = 0; j < HH; j++) {
        float w = W2[t * HH + j];
        s1 = fmaf(w, a2[j], s1);
        s2 = fmaf(w, a2[HH + j], s2);
    }
    g_c2l[t] = s1;
    g_c2r[t] = s2;
    if (t < INF_) {
        float p = 0.f, q = 0.f;
#pragma unroll 8
        for (int j = 0; j < HH; j++) {
            float w = W1[t * HH + j];
            p = fmaf(w, a1[j], p);
            q = fmaf(w, a1[HH + j], q);
        }
        g_c1l[t] = p;
        g_c1r[t] = q;
    }
}

// Softmax over 64 cols, 8 lanes per row (512 threads -> 64 rows x 8 lanes).
__device__ __forceinline__ void softmax64_w8(float* __restrict__ sAt,
                                             const float* __restrict__ sSi,
                                             const float* __restrict__ sSj, int tid) {
    int row = tid >> 3, lane = tid & 7;
    float si = sSi[row];
    const float* sj = sSj + lane * 8;
    float ev[8];
    float m = -1e30f;
#pragma unroll
    for (int j = 0; j < 8; j++) {
        float x = si + sj[j];
        x = (x > 0.f) ? x : 0.2f * x;  // leaky_relu alpha=0.2
        ev[j] = x;
        m = fmaxf(m, x);
    }
    m = fmaxf(m, __shfl_xor_sync(0xffffffffu, m, 1));
    m = fmaxf(m, __shfl_xor_sync(0xffffffffu, m, 2));
    m = fmaxf(m, __shfl_xor_sync(0xffffffffu, m, 4));
    float s = 0.f;
#pragma unroll
    for (int j = 0; j < 8; j++) {
        float e = __expf(ev[j] - m);
        ev[j] = e;
        s += e;
    }
    s += __shfl_xor_sync(0xffffffffu, s, 1);
    s += __shfl_xor_sync(0xffffffffu, s, 2);
    s += __shfl_xor_sync(0xffffffffu, s, 4);
    float inv = 1.0f / s;
    float* dst = sAt + row * ASTR + lane * 8;
#pragma unroll
    for (int j = 0; j < 8; j++) dst[j] = ev[j] * inv;
}

__device__ __forceinline__ float elu1(float x) {
    return (x > 0.f) ? x : (__expf(x) - 1.0f);
}

__global__ __launch_bounds__(NT, 2) void gat_kernel(
    const float* __restrict__ users, const float* __restrict__ W1,
    const float* __restrict__ W2,
    const float* __restrict__ mw1, const float* __restrict__ mb1,
    const float* __restrict__ mw2, const float* __restrict__ mb2,
    float* __restrict__ out, int B) {
    extern __shared__ float sm[];
    float* sWh   = sm;                    // 64*132 (Wh2)
    float* sH    = sWh + MM * STR;        // 64*132
    float* sAt   = sH + MM * STR;         // 64*68
    float* sU    = sAt + MM * ASTR;       // 192
    float* sT    = sU + 192;              // 256 (64 x 4, T = attn1 @ U, padded)
    float* sSi   = sT + 256;              // 64
    float* sSj   = sSi + 64;              // 64
    float* sC2l  = sSj + 64;              // 128
    float* sC2r  = sC2l + 128;            // 128
    float* sPoolH= sC2r + 128;            // 256 (2 halves x 128)
    float* sPool = sPoolH + 256;          // 128
    float* sR    = sPool + 128;           // 32
    float* sO    = sR + 32;               // 128
    float* sSum  = sO + 128;              // 2

    const int tid  = threadIdx.x;
    const int b    = blockIdx.x;
    // GEMM decomposition: warp tile = 32 rows x 16 cols; thread = 4 rows x 4 cols
    const int warp  = tid >> 5;
    const int lane  = tid & 31;
    const int rh    = warp >> 3;          // row half
    const int octet = warp & 7;           // col octet (16 cols)
    const int rg    = lane >> 2;          // 0..7 row sub-group
    const int cp    = lane & 3;           // 0..3 col quad
    const int c0    = octet * 16 + cp * 4;
    const int r0    = rh * 32 + rg;       // rows r0 + 8*j, j=0..3

    // ---- P0: load users + c2 vectors
    if (tid < MM * INF_) sU[tid] = users[b * (MM * INF_) + tid];
    if (tid < 128) { sC2l[tid] = g_c2l[tid]; sC2r[tid] = g_c2r[tid]; }
    __syncthreads();

    // ---- P1: layer1 si/sj via c1 trick
    if (tid < MM) {
        float u0 = sU[tid * 3], u1 = sU[tid * 3 + 1], u2 = sU[tid * 3 + 2];
        sSi[tid] = u0 * g_c1l[0] + u1 * g_c1l[1] + u2 * g_c1l[2];
        sSj[tid] = u0 * g_c1r[0] + u1 * g_c1r[1] + u2 * g_c1r[2];
    }
    __syncthreads();

    // ---- P2: softmax layer 1
    softmax64_w8(sAt, sSi, sSj, tid);
    __syncthreads();

    // ---- P3a: T = attn1 @ U (64x3; rank-3 fusion kills the 64x128x64 GEMM)
    {
        int row = tid >> 3, l8 = tid & 7;
        const float* ar = sAt + row * ASTR + l8 * 8;   // conflict-free: 272B row stride
        float t0 = 0.f, t1 = 0.f, t2 = 0.f;
#pragma unroll
        for (int j = 0; j < 8; j++) {
            float a = ar[j];
            const float* u = sU + (l8 * 8 + j) * 3;
            t0 = fmaf(a, u[0], t0);
            t1 = fmaf(a, u[1], t1);
            t2 = fmaf(a, u[2], t2);
        }
#pragma unroll
        for (int off = 1; off < 8; off <<= 1) {
            t0 += __shfl_xor_sync(0xffffffffu, t0, off);
            t1 += __shfl_xor_sync(0xffffffffu, t1, off);
            t2 += __shfl_xor_sync(0xffffffffu, t2, off);
        }
        if (!l8) {
            sT[row * 4 + 0] = t0;
            sT[row * 4 + 1] = t1;
            sT[row * 4 + 2] = t2;
            sT[row * 4 + 3] = 0.f;
        }
    }
    __syncthreads();

    // ---- P3b: h = elu(T @ W1) -> sH  (K=3)
    {
        const int d = tid & 127;
        const int q = tid >> 7;
        float w0 = W1[d], w1 = W1[HH + d], w2 = W1[2 * HH + d];
        const int i0 = q * 16;
#pragma unroll
        for (int r = 0; r < 16; r++) {
            float4 t = *(const float4*)&sT[(i0 + r) * 4];
            float x = fmaf(t.x, w0, fmaf(t.y, w1, t.z * w2));
            sH[(i0 + r) * STR + d] = elu1(x);
        }
    }
    __syncthreads();

    // ---- P4: layer2 si/sj = h @ c2 (64 rows x 8 lanes)
    {
        int row = tid >> 3, l8 = tid & 7;
        const float* hr = sH + row * STR + l8 * 16;
        const float* cl = sC2l + l8 * 16;
        const float* cr = sC2r + l8 * 16;
        float s1 = 0.f, s2 = 0.f;
#pragma unroll
        for (int k = 0; k < 16; k++) {
            float hv = hr[k];
            s1 = fmaf(hv, cl[k], s1);
            s2 = fmaf(hv, cr[k], s2);
        }
        s1 += __shfl_xor_sync(0xffffffffu, s1, 1);
        s2 += __shfl_xor_sync(0xffffffffu, s2, 1);
        s1 += __shfl_xor_sync(0xffffffffu, s1, 2);
        s2 += __shfl_xor_sync(0xffffffffu, s2, 2);
        s1 += __shfl_xor_sync(0xffffffffu, s1, 4);
        s2 += __shfl_xor_sync(0xffffffffu, s2, 4);
        if (!l8) { sSi[row] = s1; sSj[row] = s2; }
    }
    // ---- P5: Wh2 = h @ W2, K=128, cols from global (L1/L2 cached)
    {
        float4 acc[4];
#pragma unroll
        for (int j = 0; j < 4; j++) acc[j] = make_float4(0.f, 0.f, 0.f, 0.f);
#pragma unroll 4
        for (int k0 = 0; k0 < HH; k0 += 4) {
            float4 w0 = *(const float4*)&W2[(k0 + 0) * HH + c0];
            float4 w1 = *(const float4*)&W2[(k0 + 1) * HH + c0];
            float4 w2 = *(const float4*)&W2[(k0 + 2) * HH + c0];
            float4 w3 = *(const float4*)&W2[(k0 + 3) * HH + c0];
#pragma unroll
            for (int j = 0; j < 4; j++) {
                float4 h4 = *(const float4*)&sH[(r0 + 8 * j) * STR + k0];
                acc[j].x = fmaf(h4.x, w0.x, acc[j].x);
                acc[j].y = fmaf(h4.x, w0.y, acc[j].y);
                acc[j].z = fmaf(h4.x, w0.z, acc[j].z);
                acc[j].w = fmaf(h4.x, w0.w, acc[j].w);
                acc[j].x = fmaf(h4.y, w1.x, acc[j].x);
                acc[j].y = fmaf(h4.y, w1.y, acc[j].y);
                acc[j].z = fmaf(h4.y, w1.z, acc[j].z);
                acc[j].w = fmaf(h4.y, w1.w, acc[j].w);
                acc[j].x = fmaf(h4.z, w2.x, acc[j].x);
                acc[j].y = fmaf(h4.z, w2.y, acc[j].y);
                acc[j].z = fmaf(h4.z, w2.z, acc[j].z);
                acc[j].w = fmaf(h4.z, w2.w, acc[j].w);
                acc[j].x = fmaf(h4.w, w3.x, acc[j].x);
                acc[j].y = fmaf(h4.w, w3.y, acc[j].y);
                acc[j].z = fmaf(h4.w, w3.z, acc[j].z);
                acc[j].w = fmaf(h4.w, w3.w, acc[j].w);
            }
        }
#pragma unroll
        for (int j = 0; j < 4; j++)
            *(float4*)&sWh[(r0 + 8 * j) * STR + c0] = acc[j];
    }
    __syncthreads();

    // ---- P6: softmax layer 2
    softmax64_w8(sAt, sSi, sSj, tid);
    __syncthreads();

    // ---- P7: h2 = elu(attn2 @ Wh2) fused with max-pool
    {
        float4 acc[4];
#pragma unroll
        for (int j = 0; j < 4; j++) acc[j] = make_float4(0.f, 0.f, 0.f, 0.f);
#pragma unroll 4
        for (int k0 = 0; k0 < MM; k0 += 4) {
            float4 w0 = *(const float4*)&sWh[(k0 + 0) * STR + c0];
            float4 w1 = *(const float4*)&sWh[(k0 + 1) * STR + c0];
            float4 w2 = *(const float4*)&sWh[(k0 + 2) * STR + c0];
            float4 w3 = *(const float4*)&sWh[(k0 + 3) * STR + c0];
#pragma unroll
            for (int j = 0; j < 4; j++) {
                float4 a4 = *(const float4*)&sAt[(r0 + 8 * j) * ASTR + k0];
                acc[j].x = fmaf(a4.x, w0.x, acc[j].x);
                acc[j].y = fmaf(a4.x, w0.y, acc[j].y);
                acc[j].z = fmaf(a4.x, w0.z, acc[j].z);
                acc[j].w = fmaf(a4.x, w0.w, acc[j].w);
                acc[j].x = fmaf(a4.y, w1.x, acc[j].x);
                acc[j].y = fmaf(a4.y, w1.y, acc[j].y);
                acc[j].z = fmaf(a4.y, w1.z, acc[j].z);
                acc[j].w = fmaf(a4.y, w1.w, acc[j].w);
                acc[j].x = fmaf(a4.z, w2.x, acc[j].x);
                acc[j].y = fmaf(a4.z, w2.y, acc[j].y);
                acc[j].z = fmaf(a4.z, w2.z, acc[j].z);
                acc[j].w = fmaf(a4.z, w2.w, acc[j].w);
                acc[j].x = fmaf(a4.w, w3.x, acc[j].x);
                acc[j].y = fmaf(a4.w, w3.y, acc[j].y);
                acc[j].z = fmaf(a4.w, w3.z, acc[j].z);
                acc[j].w = fmaf(a4.w, w3.w, acc[j].w);
            }
        }
        float px = -1e30f, py = -1e30f, pz = -1e30f, pw = -1e30f;
#pragma unroll
        for (int j = 0; j < 4; j++) {
            px = fmaxf(px, elu1(acc[j].x));
            py = fmaxf(py, elu1(acc[j].y));
            pz = fmaxf(pz, elu1(acc[j].z));
            pw = fmaxf(pw, elu1(acc[j].w));
        }
#pragma unroll
        for (int off = 4; off < 32; off <<= 1) {
            px = fmaxf(px, __shfl_xor_sync(0xffffffffu, px, off));
            py = fmaxf(py, __shfl_xor_sync(0xffffffffu, py, off));
            pz = fmaxf(pz, __shfl_xor_sync(0xffffffffu, pz, off));
            pw = fmaxf(pw, __shfl_xor_sync(0xffffffffu, pw, off));
        }
        if (rg == 0)
            *(float4*)&sPoolH[rh * 128 + c0] = make_float4(px, py, pz, pw);
    }
    __syncthreads();

    // ---- P7b: combine the two row halves
    if (tid < 128) sPool[tid] = fmaxf(sPoolH[tid], sPoolH[128 + tid]);
    __syncthreads();

    // ---- P8: hidden = relu(pooled @ mw1 + mb1)  (32 cols x 8 lanes)
    if (tid < 256) {
        int col = tid >> 3, l8 = tid & 7;
        float acc = 0.f;
        const float* pp = sPool + l8 * 16;
#pragma unroll
        for (int k = 0; k < 16; k++) acc = fmaf(pp[k], mw1[(l8 * 16 + k) * 32 + col], acc);
        acc += __shfl_xor_sync(0xffffffffu, acc, 1);
        acc += __shfl_xor_sync(0xffffffffu, acc, 2);
        acc += __shfl_xor_sync(0xffffffffu, acc, 4);
        if (!l8) sR[col] = fmaxf(acc + mb1[col], 0.f);
    }
    __syncthreads();

    // ---- P9: readout = hidden @ mw2 + mb2; relu + eps
    if (tid < 128) {
        float acc = mb2[tid];
#pragma unroll
        for (int m = 0; m < 32; m++) acc = fmaf(sR[m], mw2[m * HH + tid], acc);
        sO[tid] = fmaxf(acc, 0.f) + 1e-6f;
    }
    __syncthreads();

    // ---- P10: sums (delta = first 64, power = last 64)
    if (tid < 2) {
        float s = 0.f;
        const float* p = sO + tid * 64;
#pragma unroll 8
        for (int j = 0; j < 64; j++) s += p[j];
        sSum[tid] = s;
    }
    __syncthreads();

    // ---- P11: normalize & write. Output layout: power[B,A] then delta[B,A]
    if (tid < 128) {
        const float Bmax = 2.0f * 50.0f - 63.0f * 0.025f;  // 98.425
        const float PMAX = 1.0f;                            // 10^(30/10-3)
        if (tid < 64) {
            out[(size_t)B * AA + (size_t)b * AA + tid] = Bmax * sO[tid] / (sSum[0] + 1e-6f);
        } else {
            out[(size_t)b * AA + (tid - 64)] = PMAX * sO[tid] / (sSum[1] + 1e-6f);
        }
    }
}

static const int SMEM_FLOATS = 2 * MM * STR + MM * ASTR + 192 + 256 + 64 + 64 + 128 + 128 + 256 + 128 + 32 + 128 + 2;

extern "C" void kernel_launch(void* const* d_in, const int* in_sizes, int n_in,
                              void* d_out, int out_size) {
    const float* users = (const float*)d_in[0];
    const float* W1    = (const float*)d_in[1];
    const float* a1    = (const float*)d_in[2];
    const float* W2    = (const float*)d_in[3];
    const float* a2    = (const float*)d_in[4];
    const float* mw1   = (const float*)d_in[5];
    const float* mb1   = (const float*)d_in[6];
    const float* mw2   = (const float*)d_in[7];
    const float* mb2   = (const float*)d_in[8];
    float* out = (float*)d_out;

    int B = in_sizes[0] / (MM * INF_);
    size_t smem = (size_t)SMEM_FLOATS * sizeof(float);

    cudaFuncSetAttribute(gat_kernel, cudaFuncAttributeMaxDynamicSharedMemorySize, (int)smem);

    precomp_kernel<<<1, 128>>>(W1, a1, W2, a2);
    gat_kernel<<<B, NT, smem>>>(users, W1, W2, mw1, mb1, mw2, mb2, out, B);
}